// round 2
// baseline (speedup 1.0000x reference)
#include <cuda_runtime.h>
#include <cuda_bf16.h>
#include <stdint.h>

// Problem constants (fixed shapes for this problem instance)
#define NU 100000
#define NI 100000
#define NN 200000               // NU + NI
#define NE 4000000
#define UD 256
#define ID 128
#define CM 64                   // COMMON == HIDDEN
#define OD 32                   // OUT
#define SCAN_BLK 1024
#define NSCAN_BLKS ((NN + SCAN_BLK - 1) / SCAN_BLK)   // 196

// ---------------- scratch (__device__ globals; no allocation) ----------------
__device__ float g_deg[NN];
__device__ float g_dinv[NN];
__device__ int   g_count[NN];
__device__ int   g_rowstart[NN + 1];
__device__ int   g_cursor[NN];
__device__ int   g_bsum[SCAN_BLK];
__device__ int   g_src32[NE];
__device__ int   g_dst32[NE];
__device__ int   g_csr_src[NE];
__device__ float g_csr_norm[NE];
__device__ float g_WuW1[UD * CM];
__device__ float g_WiW1[ID * CM];
__device__ float g_cu[CM];
__device__ float g_ci[CM];
__device__ float g_h1[(size_t)NN * CM];   // 51.2 MB  transformed features, layer 1
__device__ float g_h2[(size_t)NN * OD];   // 25.6 MB  transformed features, layer 2
__device__ int   g_is64;                  // 1 if edge_index is int64, 0 if int32

// ---------------- dtype detection for edge_index ----------------
// If int64 with values < 2^31 (node ids < 200000), all odd 32-bit words are 0.
// If int32, odd words are real node indices (prob of 2048 consecutive zeros ~ 0).
__global__ void k_detect(const int* __restrict__ ei32) {
    __shared__ int any_nonzero;
    if (threadIdx.x == 0) any_nonzero = 0;
    __syncthreads();
    int idx = 2 * threadIdx.x + 1;        // odd words among first 4096 words
    for (int i = idx; i < 4096; i += 2 * blockDim.x)
        if (ei32[i] != 0) any_nonzero = 1;
    __syncthreads();
    if (threadIdx.x == 0) g_is64 = any_nonzero ? 0 : 1;
}

// ---------------- graph preprocessing ----------------
__global__ void k_init() {
    int i = blockIdx.x * blockDim.x + threadIdx.x;
    if (i < NN) { g_deg[i] = 1.0f; g_count[i] = 0; }   // self-loop weight 1
}

__global__ void k_edge1(const int* __restrict__ ei32, const float* __restrict__ ew) {
    int e = blockIdx.x * blockDim.x + threadIdx.x;
    if (e >= NE) return;
    int s, d;
    if (g_is64) {
        s = ei32[2 * e];                      // low word of int64 (little-endian)
        d = ei32[2 * (NE + e)];
    } else {
        s = ei32[e];
        d = ei32[NE + e];
    }
    g_src32[e] = s;
    g_dst32[e] = d;
    atomicAdd(&g_count[d], 1);
    atomicAdd(&g_deg[d], ew[e]);
}

// block-local inclusive scan -> exclusive partial row_start, block totals; also dinv
__global__ void k_scan1() {
    __shared__ int sh[SCAN_BLK];
    int t = threadIdx.x;
    int gid = blockIdx.x * SCAN_BLK + t;
    int v = (gid < NN) ? g_count[gid] : 0;
    sh[t] = v;
    __syncthreads();
    for (int off = 1; off < SCAN_BLK; off <<= 1) {
        int x = (t >= off) ? sh[t - off] : 0;
        __syncthreads();
        sh[t] += x;
        __syncthreads();
    }
    if (gid < NN) {
        g_rowstart[gid] = sh[t] - v;                   // exclusive (block-local)
        float dg = g_deg[gid];
        g_dinv[gid] = (dg > 0.0f) ? rsqrtf(dg) : 0.0f;
    }
    if (t == SCAN_BLK - 1) g_bsum[blockIdx.x] = sh[t];
}

__global__ void k_scan2() {
    __shared__ int sh[SCAN_BLK];
    int t = threadIdx.x;
    int v = (t < NSCAN_BLKS) ? g_bsum[t] : 0;
    sh[t] = v;
    __syncthreads();
    for (int off = 1; off < SCAN_BLK; off <<= 1) {
        int x = (t >= off) ? sh[t - off] : 0;
        __syncthreads();
        sh[t] += x;
        __syncthreads();
    }
    if (t < NSCAN_BLKS) g_bsum[t] = sh[t] - v;         // exclusive block offsets
}

__global__ void k_scan3() {
    int i = blockIdx.x * blockDim.x + threadIdx.x;
    if (i < NN) {
        int rs = g_rowstart[i] + g_bsum[i >> 10];
        g_rowstart[i] = rs;
        g_cursor[i] = rs;
    }
    if (i == 0) g_rowstart[NN] = NE;
}

__global__ void k_scatter(const float* __restrict__ ew) {
    int e = blockIdx.x * blockDim.x + threadIdx.x;
    if (e >= NE) return;
    int s = g_src32[e];
    int d = g_dst32[e];
    float nrm = g_dinv[s] * ew[e] * g_dinv[d];
    int pos = atomicAdd(&g_cursor[d], 1);
    g_csr_src[pos] = s;
    g_csr_norm[pos] = nrm;
}

// ---------------- fold projection into first GCN transform ----------------
// WuW1 = Wu @ W1 ; WiW1 = Wi @ W1 ; cu = bu @ W1 ; ci = bi @ W1
__global__ void k_wcomb(const float* __restrict__ Wu, const float* __restrict__ bu,
                        const float* __restrict__ Wi, const float* __restrict__ bi,
                        const float* __restrict__ W1) {
    int idx = blockIdx.x * blockDim.x + threadIdx.x;
    const int TOT_U = UD * CM, TOT_I = ID * CM;
    if (idx < TOT_U) {
        int k = idx / CM, c = idx % CM;
        float a = 0.f;
        #pragma unroll
        for (int j = 0; j < CM; j++) a += Wu[k * CM + j] * W1[j * CM + c];
        g_WuW1[idx] = a;
    } else if (idx < TOT_U + TOT_I) {
        int r = idx - TOT_U;
        int k = r / CM, c = r % CM;
        float a = 0.f;
        #pragma unroll
        for (int j = 0; j < CM; j++) a += Wi[k * CM + j] * W1[j * CM + c];
        g_WiW1[r] = a;
    } else if (idx < TOT_U + TOT_I + 2 * CM) {
        int r = idx - TOT_U - TOT_I;
        if (r < CM) {
            float a = 0.f;
            #pragma unroll
            for (int j = 0; j < CM; j++) a += bu[j] * W1[j * CM + r];
            g_cu[r] = a;
        } else {
            int c = r - CM;
            float a = 0.f;
            #pragma unroll
            for (int j = 0; j < CM; j++) a += bi[j] * W1[j * CM + c];
            g_ci[c] = a;
        }
    }
}

// ---------------- embed: h1[n] = input[n] @ Wfold + cvec  (4 nodes per warp) ----------------
__global__ void k_embed(const float* __restrict__ ut, const float* __restrict__ it) {
    int tid = blockIdx.x * blockDim.x + threadIdx.x;
    int wid = tid >> 5;
    int lane = tid & 31;

    const float* in0;
    const float* W;
    const float* cvec;
    int K, node0;
    if (wid < NU / 4) {                       // user warps
        node0 = wid * 4;
        in0 = ut + (size_t)node0 * UD;
        W = g_WuW1; cvec = g_cu; K = UD;
    } else {                                  // item warps
        int m0 = (wid - NU / 4) * 4;
        node0 = NU + m0;
        in0 = it + (size_t)m0 * ID;
        W = g_WiW1; cvec = g_ci; K = ID;
    }

    float a00 = 0.f, a01 = 0.f, a10 = 0.f, a11 = 0.f, a20 = 0.f, a21 = 0.f, a30 = 0.f, a31 = 0.f;
    for (int base = 0; base < K; base += 32) {
        float v0 = in0[base + lane];
        float v1 = in0[K + base + lane];
        float v2 = in0[2 * K + base + lane];
        float v3 = in0[3 * K + base + lane];
        #pragma unroll
        for (int j = 0; j < 32; j++) {
            float w0 = W[(base + j) * CM + lane];
            float w1 = W[(base + j) * CM + 32 + lane];
            float b0 = __shfl_sync(0xffffffffu, v0, j);
            float b1 = __shfl_sync(0xffffffffu, v1, j);
            float b2 = __shfl_sync(0xffffffffu, v2, j);
            float b3 = __shfl_sync(0xffffffffu, v3, j);
            a00 = fmaf(b0, w0, a00); a01 = fmaf(b0, w1, a01);
            a10 = fmaf(b1, w0, a10); a11 = fmaf(b1, w1, a11);
            a20 = fmaf(b2, w0, a20); a21 = fmaf(b2, w1, a21);
            a30 = fmaf(b3, w0, a30); a31 = fmaf(b3, w1, a31);
        }
    }
    float c0 = cvec[lane], c1 = cvec[32 + lane];
    size_t o = (size_t)node0 * CM;
    g_h1[o + lane] = a00 + c0;           g_h1[o + 32 + lane] = a01 + c1;
    g_h1[o + CM + lane] = a10 + c0;      g_h1[o + CM + 32 + lane] = a11 + c1;
    g_h1[o + 2 * CM + lane] = a20 + c0;  g_h1[o + 2 * CM + 32 + lane] = a21 + c1;
    g_h1[o + 3 * CM + lane] = a30 + c0;  g_h1[o + 3 * CM + 32 + lane] = a31 + c1;
}

// ---------------- layer 1 aggregate + relu + b1 + @W2 fused -> h2 ----------------
__global__ void k_gather1(const float* __restrict__ b1, const float* __restrict__ W2) {
    __shared__ float sW2[CM * OD];   // 8 KB
    __shared__ float sb1[CM];
    int t = threadIdx.x;
    for (int i = t; i < CM * OD; i += blockDim.x) sW2[i] = W2[i];
    if (t < CM) sb1[t] = b1[t];
    __syncthreads();

    int node = blockIdx.x * (blockDim.x >> 5) + (t >> 5);
    int lane = t & 31;
    if (node >= NN) return;

    float dv = g_dinv[node];
    float selfw = dv * dv;
    const float* hself = g_h1 + (size_t)node * CM;
    float a0 = selfw * hself[lane];
    float a1 = selfw * hself[32 + lane];

    int beg = g_rowstart[node], end = g_rowstart[node + 1];
    for (int e = beg; e < end; e++) {
        int s = g_csr_src[e];
        float w = g_csr_norm[e];
        const float* hp = g_h1 + (size_t)s * CM;
        a0 = fmaf(w, hp[lane], a0);
        a1 = fmaf(w, hp[32 + lane], a1);
    }
    float z0 = fmaxf(a0 + sb1[lane], 0.0f);
    float z1 = fmaxf(a1 + sb1[32 + lane], 0.0f);

    // h2[node] = z @ W2   (z spread across warp: lane k holds z[k], z[k+32])
    float acc = 0.f;
    #pragma unroll
    for (int k = 0; k < 32; k++) {
        float zk0 = __shfl_sync(0xffffffffu, z0, k);
        float zk1 = __shfl_sync(0xffffffffu, z1, k);
        acc = fmaf(zk0, sW2[k * OD + lane], acc);
        acc = fmaf(zk1, sW2[(k + 32) * OD + lane], acc);
    }
    g_h2[(size_t)node * OD + lane] = acc;
}

// ---------------- layer 2 aggregate + b2 -> out ----------------
__global__ void k_gather2(const float* __restrict__ b2, float* __restrict__ out) {
    int t = threadIdx.x;
    int node = blockIdx.x * (blockDim.x >> 5) + (t >> 5);
    int lane = t & 31;
    if (node >= NN) return;

    float dv = g_dinv[node];
    float selfw = dv * dv;
    float acc = selfw * g_h2[(size_t)node * OD + lane];

    int beg = g_rowstart[node], end = g_rowstart[node + 1];
    for (int e = beg; e < end; e++) {
        int s = g_csr_src[e];
        float w = g_csr_norm[e];
        acc = fmaf(w, g_h2[(size_t)s * OD + lane], acc);
    }
    out[(size_t)node * OD + lane] = acc + b2[lane];
}

// ---------------- launch ----------------
extern "C" void kernel_launch(void* const* d_in, const int* in_sizes, int n_in,
                              void* d_out, int out_size) {
    const float* ut = (const float*)d_in[0];
    const float* it = (const float*)d_in[1];
    const int*   ei = (const int*)d_in[2];     // int32 (JAX default) or int64 low words
    const float* ew = (const float*)d_in[3];
    const float* Wu = (const float*)d_in[4];
    const float* bu = (const float*)d_in[5];
    const float* Wi = (const float*)d_in[6];
    const float* bi = (const float*)d_in[7];
    const float* W1 = (const float*)d_in[8];
    const float* b1 = (const float*)d_in[9];
    const float* W2 = (const float*)d_in[10];
    const float* b2 = (const float*)d_in[11];
    float*       out = (float*)d_out;

    // dtype detect + graph preprocessing (CSR by dst + norms)
    k_detect<<<1, 256>>>(ei);
    k_init<<<(NN + 255) / 256, 256>>>();
    k_edge1<<<(NE + 255) / 256, 256>>>(ei, ew);
    k_scan1<<<NSCAN_BLKS, SCAN_BLK>>>();
    k_scan2<<<1, SCAN_BLK>>>();
    k_scan3<<<(NN + 255) / 256, 256>>>();
    k_scatter<<<(NE + 255) / 256, 256>>>(ew);

    // weight folding (tiny)
    k_wcomb<<<(UD * CM + ID * CM + 2 * CM + 127) / 128, 128>>>(Wu, bu, Wi, bi, W1);

    // dense transforms + sparse aggregations
    k_embed<<<(NU / 4 + NI / 4) / 8, 256>>>(ut, it);          // 50000 warps, 8/block
    k_gather1<<<NN / 8, 256>>>(b1, W2);                        // 25000 blocks
    k_gather2<<<NN / 8, 256>>>(b2, out);                       // 25000 blocks
}

// round 4
// speedup vs baseline: 1.0794x; 1.0794x over previous
#include <cuda_runtime.h>
#include <cuda_bf16.h>
#include <stdint.h>

typedef unsigned long long ull;

#define NU 100000
#define NI 100000
#define NN 200000
#define NE 4000000
#define UD 256
#define ID 128
#define CM 64
#define OD 32
#define SCAN_BLK 1024
#define NSCAN_BLKS ((NN + SCAN_BLK - 1) / SCAN_BLK)

// f32x2 packed helpers
#define FMA2(d, a, b, c) asm("fma.rn.f32x2 %0, %1, %2, %3;" : "=l"(d) : "l"(a), "l"(b), "l"(c))
#define PACK2(d, x)      asm("mov.b64 %0, {%1, %1};" : "=l"(d) : "f"(x))
#define UNPACK2(lo, hi, v) asm("mov.b64 {%0, %1}, %2;" : "=f"(lo), "=f"(hi) : "l"(v))

// ---------------- scratch ----------------
__device__ float g_deg[NN];
__device__ float g_dinv[NN];
__device__ int   g_count[NN];
__device__ int   g_rowstart[NN + 1];
__device__ int   g_cursor[NN];
__device__ int   g_bsum[SCAN_BLK];
__device__ int   g_csr_src[NE];
__device__ float g_csr_norm[NE];
__device__ float g_WuW1[UD * CM];
__device__ float g_WiW1[ID * CM];
__device__ float g_cu[CM];
__device__ float g_ci[CM];
__device__ float g_h1[(size_t)NN * CM];   // 51.2 MB  embed output
__device__ float g_z1[(size_t)NN * CM];   // 51.2 MB  relu(agg1 + b1)
__device__ float g_h2[(size_t)NN * OD];   // 25.6 MB  z1 @ W2
__device__ int   g_is64;

// ---------------- dtype detection ----------------
__global__ void k_detect(const int* __restrict__ ei32) {
    __shared__ int any_nonzero;
    if (threadIdx.x == 0) any_nonzero = 0;
    __syncthreads();
    for (int i = 2 * threadIdx.x + 1; i < 4096; i += 2 * blockDim.x)
        if (ei32[i] != 0) any_nonzero = 1;
    __syncthreads();
    if (threadIdx.x == 0) g_is64 = any_nonzero ? 0 : 1;
}

// ---------------- graph preprocessing ----------------
__global__ void k_init() {
    int i = blockIdx.x * blockDim.x + threadIdx.x;
    if (i < NN) { g_deg[i] = 1.0f; g_count[i] = 0; }
}

__global__ void k_edge1(const int* __restrict__ ei32, const float* __restrict__ ew) {
    int e = blockIdx.x * blockDim.x + threadIdx.x;
    if (e >= NE) return;
    int d = g_is64 ? ei32[2 * (NE + e)] : ei32[NE + e];
    atomicAdd(&g_count[d], 1);
    atomicAdd(&g_deg[d], ew[e]);
}

__global__ void k_scan1() {
    __shared__ int sh[SCAN_BLK];
    int t = threadIdx.x;
    int gid = blockIdx.x * SCAN_BLK + t;
    int v = (gid < NN) ? g_count[gid] : 0;
    sh[t] = v;
    __syncthreads();
    for (int off = 1; off < SCAN_BLK; off <<= 1) {
        int x = (t >= off) ? sh[t - off] : 0;
        __syncthreads();
        sh[t] += x;
        __syncthreads();
    }
    if (gid < NN) {
        g_rowstart[gid] = sh[t] - v;
        float dg = g_deg[gid];
        g_dinv[gid] = (dg > 0.0f) ? rsqrtf(dg) : 0.0f;
    }
    if (t == SCAN_BLK - 1) g_bsum[blockIdx.x] = sh[t];
}

__global__ void k_scan2() {
    __shared__ int sh[SCAN_BLK];
    int t = threadIdx.x;
    int v = (t < NSCAN_BLKS) ? g_bsum[t] : 0;
    sh[t] = v;
    __syncthreads();
    for (int off = 1; off < SCAN_BLK; off <<= 1) {
        int x = (t >= off) ? sh[t - off] : 0;
        __syncthreads();
        sh[t] += x;
        __syncthreads();
    }
    if (t < NSCAN_BLKS) g_bsum[t] = sh[t] - v;
}

__global__ void k_scan3() {
    int i = blockIdx.x * blockDim.x + threadIdx.x;
    if (i < NN) {
        int rs = g_rowstart[i] + g_bsum[i >> 10];
        g_rowstart[i] = rs;
        g_cursor[i] = rs;
    }
    if (i == 0) g_rowstart[NN] = NE;
}

__global__ void k_scatter(const int* __restrict__ ei32, const float* __restrict__ ew) {
    int e = blockIdx.x * blockDim.x + threadIdx.x;
    if (e >= NE) return;
    int s, d;
    if (g_is64) { s = ei32[2 * e]; d = ei32[2 * (NE + e)]; }
    else        { s = ei32[e];     d = ei32[NE + e]; }
    float nrm = g_dinv[s] * ew[e] * g_dinv[d];
    int pos = atomicAdd(&g_cursor[d], 1);
    g_csr_src[pos] = s;
    g_csr_norm[pos] = nrm;
}

// ---------------- weight folding ----------------
__global__ void k_wcomb(const float* __restrict__ Wu, const float* __restrict__ bu,
                        const float* __restrict__ Wi, const float* __restrict__ bi,
                        const float* __restrict__ W1) {
    int idx = blockIdx.x * blockDim.x + threadIdx.x;
    const int TOT_U = UD * CM, TOT_I = ID * CM;
    if (idx < TOT_U) {
        int k = idx / CM, c = idx % CM;
        float a = 0.f;
        #pragma unroll
        for (int j = 0; j < CM; j++) a += Wu[k * CM + j] * W1[j * CM + c];
        g_WuW1[idx] = a;
    } else if (idx < TOT_U + TOT_I) {
        int r = idx - TOT_U;
        int k = r / CM, c = r % CM;
        float a = 0.f;
        #pragma unroll
        for (int j = 0; j < CM; j++) a += Wi[k * CM + j] * W1[j * CM + c];
        g_WiW1[r] = a;
    } else if (idx < TOT_U + TOT_I + 2 * CM) {
        int r = idx - TOT_U - TOT_I;
        if (r < CM) {
            float a = 0.f;
            #pragma unroll
            for (int j = 0; j < CM; j++) a += bu[j] * W1[j * CM + r];
            g_cu[r] = a;
        } else {
            int c = r - CM;
            float a = 0.f;
            #pragma unroll
            for (int j = 0; j < CM; j++) a += bi[j] * W1[j * CM + c];
            g_ci[c] = a;
        }
    }
}

// ---------------- embed: per-thread node, f32x2, smem W tiles ----------------
#define EB_THREADS 256
#define EB_KC 16
__global__ __launch_bounds__(EB_THREADS)
void k_embed(const float* __restrict__ ut, const float* __restrict__ it, int userBlocks) {
    __shared__ ulonglong2 sW[EB_KC * 16];   // 16 rows x 64 cols = 4 KB
    bool isUser = (int)blockIdx.x < userBlocks;
    int nodeLocal = (isUser ? blockIdx.x : blockIdx.x - userBlocks) * EB_THREADS + threadIdx.x;
    int K = isUser ? UD : ID;
    int Ncnt = isUser ? NU : NI;
    const float* W = isUser ? g_WuW1 : g_WiW1;
    const float* cvec = isUser ? g_cu : g_ci;
    const float* inp = isUser ? ut : it;
    bool active = nodeLocal < Ncnt;
    const float* xrow = inp + (size_t)(active ? nodeLocal : 0) * K;

    ull acc[32];
    #pragma unroll
    for (int i = 0; i < 32; i++) acc[i] = 0ull;

    for (int kb = 0; kb < K; kb += EB_KC) {
        __syncthreads();
        sW[threadIdx.x] = ((const ulonglong2*)(W + (size_t)kb * CM))[threadIdx.x];
        __syncthreads();
        if (active) {
            float x[EB_KC];
            #pragma unroll
            for (int q = 0; q < EB_KC / 4; q++) {
                float4 v = ((const float4*)(xrow + kb))[q];
                x[4 * q] = v.x; x[4 * q + 1] = v.y; x[4 * q + 2] = v.z; x[4 * q + 3] = v.w;
            }
            #pragma unroll
            for (int k = 0; k < EB_KC; k++) {
                ull bk; PACK2(bk, x[k]);
                #pragma unroll
                for (int c4 = 0; c4 < 16; c4++) {
                    ulonglong2 w = sW[k * 16 + c4];
                    FMA2(acc[2 * c4],     bk, w.x, acc[2 * c4]);
                    FMA2(acc[2 * c4 + 1], bk, w.y, acc[2 * c4 + 1]);
                }
            }
        }
    }
    if (active) {
        int node = isUser ? nodeLocal : NU + nodeLocal;
        float4* orow = (float4*)(g_h1 + (size_t)node * CM);
        #pragma unroll
        for (int c4 = 0; c4 < 16; c4++) {
            float a, b, c, d;
            UNPACK2(a, b, acc[2 * c4]);
            UNPACK2(c, d, acc[2 * c4 + 1]);
            float4 cv = ((const float4*)cvec)[c4];
            float4 ov; ov.x = a + cv.x; ov.y = b + cv.y; ov.z = c + cv.z; ov.w = d + cv.w;
            orow[c4] = ov;
        }
    }
}

// ---------------- gather1: aggregate h1 + bias + relu -> z1 (warp/node, f32x2) ----------------
__global__ void k_gather1(const float* __restrict__ b1) {
    int t = threadIdx.x;
    int node = blockIdx.x * (blockDim.x >> 5) + (t >> 5);
    int lane = t & 31;
    if (node >= NN) return;

    const ull* h = (const ull*)g_h1;    // 32 packed pairs per row
    float dv = g_dinv[node];
    ull sw; PACK2(sw, dv * dv);
    ull zero = 0ull;
    ull acc; FMA2(acc, sw, h[(size_t)node * 32 + lane], zero);

    int e = g_rowstart[node], end = g_rowstart[node + 1];
    for (; e + 4 <= end; e += 4) {
        int s0 = g_csr_src[e], s1 = g_csr_src[e + 1], s2 = g_csr_src[e + 2], s3 = g_csr_src[e + 3];
        float w0 = g_csr_norm[e], w1 = g_csr_norm[e + 1], w2 = g_csr_norm[e + 2], w3 = g_csr_norm[e + 3];
        ull v0 = h[(size_t)s0 * 32 + lane];
        ull v1 = h[(size_t)s1 * 32 + lane];
        ull v2 = h[(size_t)s2 * 32 + lane];
        ull v3 = h[(size_t)s3 * 32 + lane];
        ull p0, p1, p2, p3;
        PACK2(p0, w0); PACK2(p1, w1); PACK2(p2, w2); PACK2(p3, w3);
        FMA2(acc, p0, v0, acc);
        FMA2(acc, p1, v1, acc);
        FMA2(acc, p2, v2, acc);
        FMA2(acc, p3, v3, acc);
    }
    for (; e < end; e++) {
        int s = g_csr_src[e];
        ull p; PACK2(p, g_csr_norm[e]);
        FMA2(acc, p, h[(size_t)s * 32 + lane], acc);
    }
    float ax, ay; UNPACK2(ax, ay, acc);
    float2 bb = ((const float2*)b1)[lane];
    float2 z;
    z.x = fmaxf(ax + bb.x, 0.0f);
    z.y = fmaxf(ay + bb.y, 0.0f);
    ((float2*)(g_z1 + (size_t)node * CM))[lane] = z;
}

// ---------------- xform: h2 = z1 @ W2 (per-thread node, f32x2) ----------------
#define XF_THREADS 256
__global__ __launch_bounds__(XF_THREADS)
void k_xform(const float* __restrict__ W2) {
    __shared__ ulonglong2 sW[CM * 8];   // 64 rows x 32 cols = 8 KB = 512 ulonglong2
    sW[threadIdx.x]       = ((const ulonglong2*)W2)[threadIdx.x];
    sW[threadIdx.x + 256] = ((const ulonglong2*)W2)[threadIdx.x + 256];
    __syncthreads();

    int node = blockIdx.x * XF_THREADS + threadIdx.x;
    if (node >= NN) return;
    const float* xrow = g_z1 + (size_t)node * CM;

    ull acc[16];
    #pragma unroll
    for (int i = 0; i < 16; i++) acc[i] = 0ull;

    #pragma unroll
    for (int kb = 0; kb < CM; kb += 16) {
        float x[16];
        #pragma unroll
        for (int q = 0; q < 4; q++) {
            float4 v = ((const float4*)(xrow + kb))[q];
            x[4 * q] = v.x; x[4 * q + 1] = v.y; x[4 * q + 2] = v.z; x[4 * q + 3] = v.w;
        }
        #pragma unroll
        for (int k = 0; k < 16; k++) {
            ull bk; PACK2(bk, x[k]);
            #pragma unroll
            for (int c4 = 0; c4 < 8; c4++) {
                ulonglong2 w = sW[(kb + k) * 8 + c4];
                FMA2(acc[2 * c4],     bk, w.x, acc[2 * c4]);
                FMA2(acc[2 * c4 + 1], bk, w.y, acc[2 * c4 + 1]);
            }
        }
    }
    float4* orow = (float4*)(g_h2 + (size_t)node * OD);
    #pragma unroll
    for (int c4 = 0; c4 < 8; c4++) {
        float a, b, c, d;
        UNPACK2(a, b, acc[2 * c4]);
        UNPACK2(c, d, acc[2 * c4 + 1]);
        float4 ov; ov.x = a; ov.y = b; ov.z = c; ov.w = d;
        orow[c4] = ov;
    }
}

// ---------------- gather2: aggregate h2 + b2 -> out (dual half-warp, f32x2) ----------------
__global__ void k_gather2(const float* __restrict__ b2, float* __restrict__ out) {
    int t = threadIdx.x;
    int node = blockIdx.x * (blockDim.x >> 5) + (t >> 5);
    int lane = t & 31;
    if (node >= NN) return;
    int half = lane >> 4;
    int c = lane & 15;                      // col pair (2c, 2c+1)

    const ull* h = (const ull*)g_h2;        // 16 packed pairs per row
    ull acc = 0ull;
    if (half == 0) {
        float dv = g_dinv[node];
        ull sw; PACK2(sw, dv * dv);
        ull zero = 0ull;
        FMA2(acc, sw, h[(size_t)node * 16 + c], zero);
    }
    int beg = g_rowstart[node], end = g_rowstart[node + 1];
    int e = beg + half;
    for (; e + 2 < end; e += 4) {           // two iterations of this half's stream
        int s0 = g_csr_src[e], s1 = g_csr_src[e + 2];
        float w0 = g_csr_norm[e], w1 = g_csr_norm[e + 2];
        ull v0 = h[(size_t)s0 * 16 + c];
        ull v1 = h[(size_t)s1 * 16 + c];
        ull p0, p1; PACK2(p0, w0); PACK2(p1, w1);
        FMA2(acc, p0, v0, acc);
        FMA2(acc, p1, v1, acc);
    }
    if (e < end) {
        int s = g_csr_src[e];
        ull p; PACK2(p, g_csr_norm[e]);
        FMA2(acc, p, h[(size_t)s * 16 + c], acc);
    }
    float ax, ay; UNPACK2(ax, ay, acc);
    ax += __shfl_xor_sync(0xffffffffu, ax, 16);
    ay += __shfl_xor_sync(0xffffffffu, ay, 16);
    if (half == 0) {
        float2 bb = ((const float2*)b2)[c];
        float2 ov; ov.x = ax + bb.x; ov.y = ay + bb.y;
        ((float2*)(out + (size_t)node * OD))[c] = ov;
    }
}

// ---------------- launch ----------------
extern "C" void kernel_launch(void* const* d_in, const int* in_sizes, int n_in,
                              void* d_out, int out_size) {
    const float* ut = (const float*)d_in[0];
    const float* it = (const float*)d_in[1];
    const int*   ei = (const int*)d_in[2];
    const float* ew = (const float*)d_in[3];
    const float* Wu = (const float*)d_in[4];
    const float* bu = (const float*)d_in[5];
    const float* Wi = (const float*)d_in[6];
    const float* bi = (const float*)d_in[7];
    const float* W1 = (const float*)d_in[8];
    const float* b1 = (const float*)d_in[9];
    const float* W2 = (const float*)d_in[10];
    const float* b2 = (const float*)d_in[11];
    float*       out = (float*)d_out;

    k_detect<<<1, 256>>>(ei);
    k_init<<<(NN + 255) / 256, 256>>>();
    k_edge1<<<(NE + 255) / 256, 256>>>(ei, ew);
    k_scan1<<<NSCAN_BLKS, SCAN_BLK>>>();
    k_scan2<<<1, SCAN_BLK>>>();
    k_scan3<<<(NN + 255) / 256, 256>>>();
    k_scatter<<<(NE + 255) / 256, 256>>>(ei, ew);

    k_wcomb<<<(UD * CM + ID * CM + 2 * CM + 127) / 128, 128>>>(Wu, bu, Wi, bi, W1);

    int userBlocks = (NU + EB_THREADS - 1) / EB_THREADS;   // 391
    int itemBlocks = (NI + EB_THREADS - 1) / EB_THREADS;   // 391
    k_embed<<<userBlocks + itemBlocks, EB_THREADS>>>(ut, it, userBlocks);

    k_gather1<<<NN / 8, 256>>>(b1);
    k_xform<<<(NN + XF_THREADS - 1) / XF_THREADS, XF_THREADS>>>(W2);
    k_gather2<<<NN / 8, 256>>>(b2, out);
}

// round 5
// speedup vs baseline: 1.0990x; 1.0181x over previous
#include <cuda_runtime.h>
#include <cuda_bf16.h>
#include <stdint.h>

typedef unsigned long long ull;

#define NU 100000
#define NI 100000
#define NN 200000
#define NE 4000000
#define UD 256
#define ID 128
#define CM 64
#define OD 32
#define SCAN_BLK 1024
#define NSCAN_BLKS ((NN + SCAN_BLK - 1) / SCAN_BLK)

// f32x2 packed helpers
#define FMA2(d, a, b, c) asm("fma.rn.f32x2 %0, %1, %2, %3;" : "=l"(d) : "l"(a), "l"(b), "l"(c))
#define PACK2(d, x)      asm("mov.b64 %0, {%1, %1};" : "=l"(d) : "f"(x))
#define UNPACK2(lo, hi, v) asm("mov.b64 {%0, %1}, %2;" : "=f"(lo), "=f"(hi) : "l"(v))

// ---------------- scratch ----------------
__device__ float g_deg[NN];
__device__ float g_dinv[NN];
__device__ int   g_count[NN];
__device__ int   g_rowstart[NN + 1];
__device__ int   g_cursor[NN];
__device__ int   g_bsum[SCAN_BLK];
__device__ ull   g_csr[NE];               // packed: lo32 = src, hi32 = norm bits
__device__ float g_WuW1[UD * CM];
__device__ float g_WiW1[ID * CM];
__device__ float g_cu[CM];
__device__ float g_ci[CM];
__device__ float g_h1[(size_t)NN * CM];   // 51.2 MB
__device__ float g_z1[(size_t)NN * CM];   // 51.2 MB
__device__ float g_h2[(size_t)NN * OD];   // 25.6 MB
__device__ int   g_is64;

// ---------------- dtype detection ----------------
__global__ void k_detect(const int* __restrict__ ei32) {
    __shared__ int any_nonzero;
    if (threadIdx.x == 0) any_nonzero = 0;
    __syncthreads();
    for (int i = 2 * threadIdx.x + 1; i < 4096; i += 2 * blockDim.x)
        if (ei32[i] != 0) any_nonzero = 1;
    __syncthreads();
    if (threadIdx.x == 0) g_is64 = any_nonzero ? 0 : 1;
}

__global__ void k_init() {
    int i = blockIdx.x * blockDim.x + threadIdx.x;
    if (i < NN) { g_deg[i] = 1.0f; g_count[i] = 0; }
}

// ---------------- weight folding ----------------
__global__ void k_wcomb(const float* __restrict__ Wu, const float* __restrict__ bu,
                        const float* __restrict__ Wi, const float* __restrict__ bi,
                        const float* __restrict__ W1) {
    int idx = blockIdx.x * blockDim.x + threadIdx.x;
    const int TOT_U = UD * CM, TOT_I = ID * CM;
    if (idx < TOT_U) {
        int k = idx / CM, c = idx % CM;
        float a = 0.f;
        #pragma unroll
        for (int j = 0; j < CM; j++) a += Wu[k * CM + j] * W1[j * CM + c];
        g_WuW1[idx] = a;
    } else if (idx < TOT_U + TOT_I) {
        int r = idx - TOT_U;
        int k = r / CM, c = r % CM;
        float a = 0.f;
        #pragma unroll
        for (int j = 0; j < CM; j++) a += Wi[k * CM + j] * W1[j * CM + c];
        g_WiW1[r] = a;
    } else if (idx < TOT_U + TOT_I + 2 * CM) {
        int r = idx - TOT_U - TOT_I;
        if (r < CM) {
            float a = 0.f;
            #pragma unroll
            for (int j = 0; j < CM; j++) a += bu[j] * W1[j * CM + r];
            g_cu[r] = a;
        } else {
            int c = r - CM;
            float a = 0.f;
            #pragma unroll
            for (int j = 0; j < CM; j++) a += bi[j] * W1[j * CM + c];
            g_ci[c] = a;
        }
    }
}

// ---------------- embed: per-thread node, f32x2, smem W tiles ----------------
#define EB_THREADS 256
#define EB_KC 16
__global__ __launch_bounds__(EB_THREADS)
void k_embed(const float* __restrict__ ut, const float* __restrict__ it, int userBlocks) {
    __shared__ ulonglong2 sW[EB_KC * 16];   // 16 rows x 64 cols = 4 KB
    bool isUser = (int)blockIdx.x < userBlocks;
    int nodeLocal = (isUser ? blockIdx.x : blockIdx.x - userBlocks) * EB_THREADS + threadIdx.x;
    int K = isUser ? UD : ID;
    int Ncnt = isUser ? NU : NI;
    const float* W = isUser ? g_WuW1 : g_WiW1;
    const float* cvec = isUser ? g_cu : g_ci;
    const float* inp = isUser ? ut : it;
    bool active = nodeLocal < Ncnt;
    const float* xrow = inp + (size_t)(active ? nodeLocal : 0) * K;

    ull acc[32];
    #pragma unroll
    for (int i = 0; i < 32; i++) acc[i] = 0ull;

    for (int kb = 0; kb < K; kb += EB_KC) {
        __syncthreads();
        sW[threadIdx.x] = ((const ulonglong2*)(W + (size_t)kb * CM))[threadIdx.x];
        __syncthreads();
        if (active) {
            float x[EB_KC];
            #pragma unroll
            for (int q = 0; q < EB_KC / 4; q++) {
                float4 v = ((const float4*)(xrow + kb))[q];
                x[4 * q] = v.x; x[4 * q + 1] = v.y; x[4 * q + 2] = v.z; x[4 * q + 3] = v.w;
            }
            #pragma unroll
            for (int k = 0; k < EB_KC; k++) {
                ull bk; PACK2(bk, x[k]);
                #pragma unroll
                for (int c4 = 0; c4 < 16; c4++) {
                    ulonglong2 w = sW[k * 16 + c4];
                    FMA2(acc[2 * c4],     bk, w.x, acc[2 * c4]);
                    FMA2(acc[2 * c4 + 1], bk, w.y, acc[2 * c4 + 1]);
                }
            }
        }
    }
    if (active) {
        int node = isUser ? nodeLocal : NU + nodeLocal;
        float4* orow = (float4*)(g_h1 + (size_t)node * CM);
        #pragma unroll
        for (int c4 = 0; c4 < 16; c4++) {
            float a, b, c, d;
            UNPACK2(a, b, acc[2 * c4]);
            UNPACK2(c, d, acc[2 * c4 + 1]);
            float4 cv = ((const float4*)cvec)[c4];
            float4 ov; ov.x = a + cv.x; ov.y = b + cv.y; ov.z = c + cv.z; ov.w = d + cv.w;
            orow[c4] = ov;
        }
    }
}

// ---------------- graph preprocessing ----------------
// 2 edges per thread; adjacent loads merge into int2/int4
__global__ void k_edge1(const int* __restrict__ ei32, const float* __restrict__ ew) {
    int t = blockIdx.x * blockDim.x + threadIdx.x;
    int e = 2 * t;
    if (e >= NE) return;
    int d0, d1;
    if (g_is64) {
        int4 v = *(const int4*)(ei32 + 2 * (NE + e));   // words 4t..4t+3 of dst region
        d0 = v.x; d1 = v.z;
    } else {
        int2 v = *(const int2*)(ei32 + NE + e);
        d0 = v.x; d1 = v.y;
    }
    float2 w = *(const float2*)(ew + e);
    atomicAdd(&g_count[d0], 1);
    atomicAdd(&g_deg[d0], w.x);
    atomicAdd(&g_count[d1], 1);
    atomicAdd(&g_deg[d1], w.y);
}

__global__ void k_scan1() {
    __shared__ int sh[SCAN_BLK];
    int t = threadIdx.x;
    int gid = blockIdx.x * SCAN_BLK + t;
    int v = (gid < NN) ? g_count[gid] : 0;
    sh[t] = v;
    __syncthreads();
    for (int off = 1; off < SCAN_BLK; off <<= 1) {
        int x = (t >= off) ? sh[t - off] : 0;
        __syncthreads();
        sh[t] += x;
        __syncthreads();
    }
    if (gid < NN) {
        g_rowstart[gid] = sh[t] - v;
        float dg = g_deg[gid];
        g_dinv[gid] = (dg > 0.0f) ? rsqrtf(dg) : 0.0f;
    }
    if (t == SCAN_BLK - 1) g_bsum[blockIdx.x] = sh[t];
}

__global__ void k_scan2() {
    __shared__ int sh[SCAN_BLK];
    int t = threadIdx.x;
    int v = (t < NSCAN_BLKS) ? g_bsum[t] : 0;
    sh[t] = v;
    __syncthreads();
    for (int off = 1; off < SCAN_BLK; off <<= 1) {
        int x = (t >= off) ? sh[t - off] : 0;
        __syncthreads();
        sh[t] += x;
        __syncthreads();
    }
    if (t < NSCAN_BLKS) g_bsum[t] = sh[t] - v;
}

__global__ void k_scan3() {
    int i = blockIdx.x * blockDim.x + threadIdx.x;
    if (i < NN) {
        int rs = g_rowstart[i] + g_bsum[i >> 10];
        g_rowstart[i] = rs;
        g_cursor[i] = rs;
    }
    if (i == 0) g_rowstart[NN] = NE;
}

__global__ void k_scatter(const int* __restrict__ ei32, const float* __restrict__ ew) {
    int e = blockIdx.x * blockDim.x + threadIdx.x;
    if (e >= NE) return;
    int s, d;
    if (g_is64) { s = ei32[2 * e]; d = ei32[2 * (NE + e)]; }
    else        { s = ei32[e];     d = ei32[NE + e]; }
    float nrm = g_dinv[s] * ew[e] * g_dinv[d];
    int pos = atomicAdd(&g_cursor[d], 1);
    g_csr[pos] = (ull)(unsigned)s | ((ull)__float_as_uint(nrm) << 32);   // one 8B store
}

// ---------------- gather1: aggregate h1 + bias + relu -> z1 (warp/node, f32x2) ----------------
__global__ void k_gather1(const float* __restrict__ b1) {
    int t = threadIdx.x;
    int node = blockIdx.x * (blockDim.x >> 5) + (t >> 5);
    int lane = t & 31;
    if (node >= NN) return;

    const ull* h = (const ull*)g_h1;    // 32 packed pairs per row
    float dv = g_dinv[node];
    ull sw; PACK2(sw, dv * dv);
    ull zero = 0ull;
    ull acc; FMA2(acc, sw, h[(size_t)node * 32 + lane], zero);

    int e = g_rowstart[node], end = g_rowstart[node + 1];
    for (; e + 4 <= end; e += 4) {
        ull p0 = g_csr[e], p1 = g_csr[e + 1], p2 = g_csr[e + 2], p3 = g_csr[e + 3];
        int s0 = (int)(unsigned)p0, s1 = (int)(unsigned)p1;
        int s2 = (int)(unsigned)p2, s3 = (int)(unsigned)p3;
        ull v0 = h[(size_t)s0 * 32 + lane];
        ull v1 = h[(size_t)s1 * 32 + lane];
        ull v2 = h[(size_t)s2 * 32 + lane];
        ull v3 = h[(size_t)s3 * 32 + lane];
        float w0 = __uint_as_float((unsigned)(p0 >> 32));
        float w1 = __uint_as_float((unsigned)(p1 >> 32));
        float w2 = __uint_as_float((unsigned)(p2 >> 32));
        float w3 = __uint_as_float((unsigned)(p3 >> 32));
        ull q0, q1, q2, q3;
        PACK2(q0, w0); PACK2(q1, w1); PACK2(q2, w2); PACK2(q3, w3);
        FMA2(acc, q0, v0, acc);
        FMA2(acc, q1, v1, acc);
        FMA2(acc, q2, v2, acc);
        FMA2(acc, q3, v3, acc);
    }
    for (; e < end; e++) {
        ull p = g_csr[e];
        int s = (int)(unsigned)p;
        float w = __uint_as_float((unsigned)(p >> 32));
        ull q; PACK2(q, w);
        FMA2(acc, q, h[(size_t)s * 32 + lane], acc);
    }
    float ax, ay; UNPACK2(ax, ay, acc);
    float2 bb = ((const float2*)b1)[lane];
    float2 z;
    z.x = fmaxf(ax + bb.x, 0.0f);
    z.y = fmaxf(ay + bb.y, 0.0f);
    ((float2*)(g_z1 + (size_t)node * CM))[lane] = z;
}

// ---------------- xform: h2 = z1 @ W2 (per-thread node, f32x2) ----------------
#define XF_THREADS 256
__global__ __launch_bounds__(XF_THREADS)
void k_xform(const float* __restrict__ W2) {
    __shared__ ulonglong2 sW[CM * 8];   // 64 rows x 32 cols = 8 KB = 512 ulonglong2
    sW[threadIdx.x]       = ((const ulonglong2*)W2)[threadIdx.x];
    sW[threadIdx.x + 256] = ((const ulonglong2*)W2)[threadIdx.x + 256];
    __syncthreads();

    int node = blockIdx.x * XF_THREADS + threadIdx.x;
    if (node >= NN) return;
    const float* xrow = g_z1 + (size_t)node * CM;

    ull acc[16];
    #pragma unroll
    for (int i = 0; i < 16; i++) acc[i] = 0ull;

    #pragma unroll
    for (int kb = 0; kb < CM; kb += 16) {
        float x[16];
        #pragma unroll
        for (int q = 0; q < 4; q++) {
            float4 v = ((const float4*)(xrow + kb))[q];
            x[4 * q] = v.x; x[4 * q + 1] = v.y; x[4 * q + 2] = v.z; x[4 * q + 3] = v.w;
        }
        #pragma unroll
        for (int k = 0; k < 16; k++) {
            ull bk; PACK2(bk, x[k]);
            #pragma unroll
            for (int c4 = 0; c4 < 8; c4++) {
                ulonglong2 w = sW[(kb + k) * 8 + c4];
                FMA2(acc[2 * c4],     bk, w.x, acc[2 * c4]);
                FMA2(acc[2 * c4 + 1], bk, w.y, acc[2 * c4 + 1]);
            }
        }
    }
    float4* orow = (float4*)(g_h2 + (size_t)node * OD);
    #pragma unroll
    for (int c4 = 0; c4 < 8; c4++) {
        float a, b, c, d;
        UNPACK2(a, b, acc[2 * c4]);
        UNPACK2(c, d, acc[2 * c4 + 1]);
        float4 ov; ov.x = a; ov.y = b; ov.z = c; ov.w = d;
        orow[c4] = ov;
    }
}

// ---------------- gather2: aggregate h2 + b2 -> out (dual half-warp, f32x2) ----------------
__global__ void k_gather2(const float* __restrict__ b2, float* __restrict__ out) {
    int t = threadIdx.x;
    int node = blockIdx.x * (blockDim.x >> 5) + (t >> 5);
    int lane = t & 31;
    if (node >= NN) return;
    int half = lane >> 4;
    int c = lane & 15;                      // col pair (2c, 2c+1)

    const ull* h = (const ull*)g_h2;        // 16 packed pairs per row
    ull acc = 0ull;
    if (half == 0) {
        float dv = g_dinv[node];
        ull sw; PACK2(sw, dv * dv);
        ull zero = 0ull;
        FMA2(acc, sw, h[(size_t)node * 16 + c], zero);
    }
    int beg = g_rowstart[node], end = g_rowstart[node + 1];
    int e = beg + half;
    for (; e + 2 < end; e += 4) {
        ull p0 = g_csr[e], p1 = g_csr[e + 2];
        int s0 = (int)(unsigned)p0, s1 = (int)(unsigned)p1;
        ull v0 = h[(size_t)s0 * 16 + c];
        ull v1 = h[(size_t)s1 * 16 + c];
        float w0 = __uint_as_float((unsigned)(p0 >> 32));
        float w1 = __uint_as_float((unsigned)(p1 >> 32));
        ull q0, q1; PACK2(q0, w0); PACK2(q1, w1);
        FMA2(acc, q0, v0, acc);
        FMA2(acc, q1, v1, acc);
    }
    if (e < end) {
        ull p = g_csr[e];
        int s = (int)(unsigned)p;
        float w = __uint_as_float((unsigned)(p >> 32));
        ull q; PACK2(q, w);
        FMA2(acc, q, h[(size_t)s * 16 + c], acc);
    }
    float ax, ay; UNPACK2(ax, ay, acc);
    ax += __shfl_xor_sync(0xffffffffu, ax, 16);
    ay += __shfl_xor_sync(0xffffffffu, ay, 16);
    if (half == 0) {
        float2 bb = ((const float2*)b2)[c];
        float2 ov; ov.x = ax + bb.x; ov.y = ay + bb.y;
        ((float2*)(out + (size_t)node * OD))[c] = ov;
    }
}

// ---------------- launch ----------------
extern "C" void kernel_launch(void* const* d_in, const int* in_sizes, int n_in,
                              void* d_out, int out_size) {
    const float* ut = (const float*)d_in[0];
    const float* it = (const float*)d_in[1];
    const int*   ei = (const int*)d_in[2];
    const float* ew = (const float*)d_in[3];
    const float* Wu = (const float*)d_in[4];
    const float* bu = (const float*)d_in[5];
    const float* Wi = (const float*)d_in[6];
    const float* bi = (const float*)d_in[7];
    const float* W1 = (const float*)d_in[8];
    const float* b1 = (const float*)d_in[9];
    const float* W2 = (const float*)d_in[10];
    const float* b2 = (const float*)d_in[11];
    float*       out = (float*)d_out;

    int userBlocks = (NU + EB_THREADS - 1) / EB_THREADS;
    int itemBlocks = (NI + EB_THREADS - 1) / EB_THREADS;

    // launch order arranged so k_embed is the 4th launch (ncu capture slot)
    k_detect<<<1, 256>>>(ei);                                              // 1
    k_init<<<(NN + 255) / 256, 256>>>();                                   // 2
    k_wcomb<<<(UD * CM + ID * CM + 2 * CM + 127) / 128, 128>>>(Wu, bu, Wi, bi, W1); // 3
    k_embed<<<userBlocks + itemBlocks, EB_THREADS>>>(ut, it, userBlocks);  // 4  <- profiled
    k_edge1<<<(NE / 2 + 255) / 256, 256>>>(ei, ew);                        // 5
    k_scan1<<<NSCAN_BLKS, SCAN_BLK>>>();                                   // 6
    k_scan2<<<1, SCAN_BLK>>>();                                            // 7
    k_scan3<<<(NN + 255) / 256, 256>>>();                                  // 8
    k_scatter<<<(NE + 255) / 256, 256>>>(ei, ew);                          // 9
    k_gather1<<<NN / 8, 256>>>(b1);                                        // 10
    k_xform<<<(NN + XF_THREADS - 1) / XF_THREADS, XF_THREADS>>>(W2);       // 11
    k_gather2<<<NN / 8, 256>>>(b2, out);                                   // 12
}